// round 2
// baseline (speedup 1.0000x reference)
#include <cuda_runtime.h>
#include <cstdint>

#define N_NODES 50000
#define N_EDGES 800000
#define DIM     64
#define NLAYERS 3

// Scratch (no cudaMalloc allowed).
__device__ float  g_bufA[N_NODES * DIM];
__device__ float  g_bufB[N_NODES * DIM];
__device__ float  g_agg [N_NODES * DIM];
__device__ int    g_off [N_NODES + 1];
__device__ int    g_cur [N_NODES];
__device__ float2 g_epk [N_EDGES];     // (.x = src index as int bits, .y = weight)

// ---------------------------------------------------------------------------
// CSR build (per call; reused by all 3 layers)
// ---------------------------------------------------------------------------
__global__ void csr_zero_kernel() {
    int i = blockIdx.x * blockDim.x + threadIdx.x;
    if (i < N_NODES) g_cur[i] = 0;
}

__global__ void csr_hist_kernel(const int* __restrict__ dst) {
    int e = blockIdx.x * blockDim.x + threadIdx.x;
    if (e < N_EDGES) atomicAdd(&g_cur[dst[e]], 1);
}

// Single block, 1024 threads: exclusive scan of g_cur -> g_off, zero g_cur.
__global__ __launch_bounds__(1024) void csr_scan_kernel() {
    __shared__ int sums[1024];
    const int t  = threadIdx.x;
    const int CH = (N_NODES + 1023) / 1024;     // 49
    int lo = t * CH;
    int hi = lo + CH; if (hi > N_NODES) hi = N_NODES;
    if (lo > N_NODES) lo = N_NODES;

    int s = 0;
    for (int i = lo; i < hi; i++) s += g_cur[i];
    sums[t] = s;
    __syncthreads();
    // Hillis-Steele inclusive scan
    #pragma unroll
    for (int off = 1; off < 1024; off <<= 1) {
        int v = (t >= off) ? sums[t - off] : 0;
        __syncthreads();
        sums[t] += v;
        __syncthreads();
    }
    int run = (t == 0) ? 0 : sums[t - 1];       // exclusive prefix
    for (int i = lo; i < hi; i++) {
        int c = g_cur[i];
        g_off[i] = run;
        run += c;
        g_cur[i] = 0;
    }
    if (t == 1023) g_off[N_NODES] = run;        // == N_EDGES
}

__global__ void csr_fill_kernel(const int* __restrict__ src,
                                const int* __restrict__ dst,
                                const float* __restrict__ ew) {
    int e = blockIdx.x * blockDim.x + threadIdx.x;
    if (e >= N_EDGES) return;
    int d = dst[e];
    int pos = g_off[d] + atomicAdd(&g_cur[d], 1);
    g_epk[pos] = make_float2(__int_as_float(src[e]), ew[e]);
}

// ---------------------------------------------------------------------------
// Pull aggregation: agg[n] = sum_{j in CSR[n]} w_j * h[src_j].
// 16 threads per node, one float4 lane each. No atomics, no pre-zeroing.
// ---------------------------------------------------------------------------
__global__ __launch_bounds__(256) void pull_kernel(
    const float4* __restrict__ h,
    float4*       __restrict__ agg)
{
    int t = blockIdx.x * blockDim.x + threadIdx.x;
    int n = t >> 4;
    if (n >= N_NODES) return;
    int lane = t & 15;

    int beg = __ldg(g_off + n);
    int end = __ldg(g_off + n + 1);

    float4 acc = make_float4(0.f, 0.f, 0.f, 0.f);
    for (int j = beg; j < end; j++) {
        float2 ep = __ldg(g_epk + j);               // uniform across the 16
        int   s = __float_as_int(ep.x);
        float w = ep.y;
        float4 v = __ldg(h + (size_t)s * 16 + lane);
        acc.x += w * v.x; acc.y += w * v.y;
        acc.z += w * v.z; acc.w += w * v.w;
    }
    agg[(size_t)n * 16 + lane] = acc;
}

// ---------------------------------------------------------------------------
// Fused dual GEMM: out = [H|AGG](K=128) @ [Wroot;Wrel] + bias (tanh optional)
// 256 threads, 64x64 tile, 4x4 per thread, W in SMEM.
// ---------------------------------------------------------------------------
__global__ __launch_bounds__(256) void gemm_kernel(
    const float* __restrict__ H,
    const float* __restrict__ AGG,
    const float* __restrict__ Wroot,   // [64][64]
    const float* __restrict__ Wrel,    // [64][64]
    const float* __restrict__ bias,    // [64]
    float*       __restrict__ out,
    int doTanh)
{
    __shared__ float Ws[128][64];   // k<64: Wroot, k>=64: Wrel
    __shared__ float As[16][68];    // [kk][row], padded

    const int tid = threadIdx.x;
    const int ty  = tid >> 4;
    const int tx  = tid & 15;
    const int rowBase = blockIdx.x * 64;

    #pragma unroll
    for (int it = 0; it < 8; it++) {
        int f4 = tid + it * 256;
        int k  = f4 >> 4;
        int jq = f4 & 15;
        const float* srcw = (k < 64) ? (Wroot + k * 64 + jq * 4)
                                     : (Wrel + (k - 64) * 64 + jq * 4);
        float4 wv = __ldg((const float4*)srcw);
        *(float4*)&Ws[k][jq * 4] = wv;
    }

    float acc[4][4];
    #pragma unroll
    for (int i = 0; i < 4; i++)
        #pragma unroll
        for (int j = 0; j < 4; j++) acc[i][j] = 0.f;

    const int ldRow   = tid >> 2;
    const int ldKpart = (tid & 3) * 4;
    const int gRow    = rowBase + ldRow;
    const bool rowOk  = (gRow < N_NODES);

    #pragma unroll 1
    for (int kc = 0; kc < 8; kc++) {
        __syncthreads();
        const float* srcA = (kc < 4) ? H : AGG;
        int kLocal = (kc & 3) * 16 + ldKpart;
        float4 av = make_float4(0.f, 0.f, 0.f, 0.f);
        if (rowOk) av = __ldg((const float4*)(srcA + (size_t)gRow * 64 + kLocal));
        As[ldKpart + 0][ldRow] = av.x;
        As[ldKpart + 1][ldRow] = av.y;
        As[ldKpart + 2][ldRow] = av.z;
        As[ldKpart + 3][ldRow] = av.w;
        __syncthreads();

        #pragma unroll
        for (int kk = 0; kk < 16; kk++) {
            float4 a = *(const float4*)&As[kk][ty * 4];
            float4 b = *(const float4*)&Ws[kc * 16 + kk][tx * 4];
            acc[0][0] += a.x * b.x; acc[0][1] += a.x * b.y;
            acc[0][2] += a.x * b.z; acc[0][3] += a.x * b.w;
            acc[1][0] += a.y * b.x; acc[1][1] += a.y * b.y;
            acc[1][2] += a.y * b.z; acc[1][3] += a.y * b.w;
            acc[2][0] += a.z * b.x; acc[2][1] += a.z * b.y;
            acc[2][2] += a.z * b.z; acc[2][3] += a.z * b.w;
            acc[3][0] += a.w * b.x; acc[3][1] += a.w * b.y;
            acc[3][2] += a.w * b.z; acc[3][3] += a.w * b.w;
        }
    }

    float4 bv = __ldg((const float4*)(bias + tx * 4));

    #pragma unroll
    for (int i = 0; i < 4; i++) {
        int r = rowBase + ty * 4 + i;
        if (r >= N_NODES) break;
        float4 o;
        o.x = acc[i][0] + bv.x;
        o.y = acc[i][1] + bv.y;
        o.z = acc[i][2] + bv.z;
        o.w = acc[i][3] + bv.w;
        if (doTanh) {
            o.x = tanhf(o.x); o.y = tanhf(o.y);
            o.z = tanhf(o.z); o.w = tanhf(o.w);
        }
        *(float4*)(out + (size_t)r * 64 + tx * 4) = o;
    }
}

// ---------------------------------------------------------------------------
// Launcher
// ---------------------------------------------------------------------------
extern "C" void kernel_launch(void* const* d_in, const int* in_sizes, int n_in,
                              void* d_out, int out_size)
{
    const float* x      = (const float*)d_in[0];   // [N, 64]
    const int*   eidx   = (const int*)  d_in[1];   // [2, E]
    const float* ew     = (const float*)d_in[2];   // [E]
    const float* W_rel  = (const float*)d_in[3];   // [L, 64, 64]
    const float* b_rel  = (const float*)d_in[4];   // [L, 64]
    const float* W_root = (const float*)d_in[5];   // [L, 64, 64]
    float* out = (float*)d_out;

    const int* src = eidx;            // row 0
    const int* dst = eidx + N_EDGES;  // row 1

    float *pA, *pB, *pAgg;
    cudaGetSymbolAddress((void**)&pA,   g_bufA);
    cudaGetSymbolAddress((void**)&pB,   g_bufB);
    cudaGetSymbolAddress((void**)&pAgg, g_agg);

    const int edgeBlocks = (N_EDGES + 255) / 256;           // 3125
    const int nodeBlocks = (N_NODES + 255) / 256;           // 196
    const int pullBlocks = (N_NODES * 16 + 255) / 256;      // 3125
    const int gemmBlocks = (N_NODES + 63) / 64;             // 782

    // Build CSR by dst (once per call; used by all layers).
    csr_zero_kernel<<<nodeBlocks, 256>>>();
    csr_hist_kernel<<<edgeBlocks, 256>>>(dst);
    csr_scan_kernel<<<1, 1024>>>();
    csr_fill_kernel<<<edgeBlocks, 256>>>(src, dst, ew);

    const float* hprev = x;
    for (int layer = 0; layer < NLAYERS; layer++) {
        float* hnext = (layer == NLAYERS - 1) ? out : ((layer == 0) ? pA : pB);

        pull_kernel<<<pullBlocks, 256>>>((const float4*)hprev, (float4*)pAgg);
        gemm_kernel<<<gemmBlocks, 256>>>(
            hprev, pAgg,
            W_root + (size_t)layer * DIM * DIM,
            W_rel  + (size_t)layer * DIM * DIM,
            b_rel  + (size_t)layer * DIM,
            hnext,
            layer == NLAYERS - 1 ? 1 : 0);

        hprev = hnext;
    }
}